// round 17
// baseline (speedup 1.0000x reference)
#include <cuda_runtime.h>
#include <cuda_fp16.h>

#define BB 128
#define TT 256
#define KDIM 50
#define KK 2500
#define START_TAG 48
#define END_TAG 49
#define NTH 256
#define SLACK 4.0f
#define PBS 27            // Pb row stride in half2 units (conflict-free scalar reads)

__device__ float g_apart[BB];
__device__ float g_gpart[BB];
__device__ int   g_count = 0;

__device__ __forceinline__ float ex2f(float x) {
    float y; asm("ex2.approx.f32 %0, %1;" : "=f"(y) : "f"(x)); return y;
}
__device__ __forceinline__ float lg2f(float x) {
    float y; asm("lg2.approx.f32 %0, %1;" : "=f"(y) : "f"(x)); return y;
}
__device__ __forceinline__ unsigned pack_ex2_h2(float x1, float x2) {
    unsigned p, e;
    asm("cvt.rn.f16x2.f32 %0, %1, %2;" : "=r"(p) : "f"(x2), "f"(x1));
    asm("ex2.approx.f16x2 %0, %1;" : "=r"(e) : "r"(p));
    return e;             // half2 (exp2(x1), exp2(x2))
}
__device__ __forceinline__ __half2 u2h(unsigned u) { return *reinterpret_cast<__half2*>(&u); }
__device__ __forceinline__ void pfL2(const void* p) {
    asm volatile("prefetch.global.L2 [%0];" :: "l"(p));
}

__global__ __launch_bounds__(NTH, 1)
void viterbi_gemv_kernel(const float* __restrict__ scores,
                         const int* __restrict__ targets,
                         const int* __restrict__ lengths,
                         float* __restrict__ out) {
    __shared__ __align__(16) unsigned Pf[2][25 * 64];   // fwd: (j-pair, col) half2
    __shared__ __align__(16) unsigned Pb[2][50 * PBS];  // bwd: (row, k-pair) half2
    __shared__ __align__(16) __half wf[2][64];          // fwd weights exp2(ab_j)
    __shared__ __align__(16) __half wb[2][64];          // bwd weights
    __shared__ float r0s[2][2];                         // stale anchors
    __shared__ float mxi[2];
    __shared__ float avecs[2][64];
    __shared__ float goldS[2];
    __shared__ int   sFin;
    __shared__ float sa[8], sg[8];

    const int b    = blockIdx.x;
    const int tid  = threadIdx.x;
    const int lane = tid & 31;
    const int wid  = tid >> 5;
    const int len  = lengths[b];
    const int m    = (len + 1) >> 1;
    const int nvF  = m;
    const int nvB  = len - m + 1;
    const float* base = scores + (size_t)b * TT * KK;
    const int* tgp = targets + b * TT;
    const float L = 1.4426950408889634f;

    float r = 0.f, shift = 0.f, dcur = 0.f, gold = 0.f, gpend = 0.f;
    float2 A[10], B[10];      // fwd converter staging (live only in wid 4-5)
    float2 C[20];             // bwd converter staging (wid 6-7)
    const int c   = tid & 63;
    const int cc  = (c < KDIM) ? c : 0;
    const int ctf = tid - 128;        // fwd converter index (wid 4-5)
    const int ctb = tid - 192;        // bwd converter index (wid 6-7)

    // ================= prologue =================
    if (wid < 2) {                    // fwd compute init
        r = (c < KDIM) ? __ldg(base + START_TAG * KDIM + c) * L : -1e30f;
        float mw = r;
        #pragma unroll
        for (int o = 16; o > 0; o >>= 1)
            mw = fmaxf(mw, __shfl_xor_sync(0xFFFFFFFFu, mw, o));
        if (lane == 0) mxi[wid] = mw;
    } else if (wid < 4) {             // bwd compute init
        r = (c == END_TAG) ? 0.f : -1e30f;
    } else if (wid < 6) {             // fwd converters: stage tile 1, prefetch 2,3
        if (1 < nvF) {
            #pragma unroll
            for (int u = 0; u < 10; ++u) {
                int e = ctf + u * 64;
                if (e < 625) {
                    int j2 = e / 25, c2 = e - j2 * 25;
                    const float2* s = (const float2*)(base + (size_t)1 * KK + (2 * j2) * KDIM) + c2;
                    A[u] = __ldg(s); B[u] = __ldg(s + 25);
                }
            }
        }
        if (2 < nvF) { const char* p = (const char*)(base + (size_t)2 * KK);
                       pfL2(p + ctf * 128); if (ctf < 15) pfL2(p + (ctf + 64) * 128); }
        if (3 < nvF) { const char* p = (const char*)(base + (size_t)3 * KK);
                       pfL2(p + ctf * 128); if (ctf < 15) pfL2(p + (ctf + 64) * 128); }
    } else {                          // bwd converters: stage tile len-1, prefetch
        if (1 < nvB) {
            #pragma unroll
            for (int u = 0; u < 20; ++u) {
                int e = ctb + u * 64;
                if (e < 1250) {
                    int rr = e / 25, k2 = e - rr * 25;
                    C[u] = __ldg((const float2*)(base + (size_t)(len - 1) * KK + rr * KDIM) + k2);
                }
            }
        }
        if (2 < nvB) { const char* p = (const char*)(base + (size_t)(len - 2) * KK);
                       pfL2(p + ctb * 128); if (ctb < 15) pfL2(p + (ctb + 64) * 128); }
        if (3 < nvB) { const char* p = (const char*)(base + (size_t)(len - 3) * KK);
                       pfL2(p + ctb * 128); if (ctb < 15) pfL2(p + (ctb + 64) * 128); }
    }
    __syncthreads();                  // mxi visible

    if (wid < 2) {                    // fwd: anchor + initial weights
        dcur = fmaxf(mxi[0], mxi[1]) + SLACK;
        wf[1][c] = __float2half_rn(ex2f(fminf(r - dcur, 4.0f)));
        if (tid == 0) r0s[0][0] = r;  // lane c==0 holds alpha0[0]
    } else if (wid < 4) {
        dcur = 0.f;
        wb[1][c] = __float2half_rn((c == END_TAG) ? 1.0f : 0.0f);
        if (tid == 64) r0s[1][0] = 0.f;
    } else if (wid < 6) {             // fwd conv: convert tile1 -> Pf[1]; stage tile2; gold
        if (1 < nvF) {
            #pragma unroll
            for (int u = 0; u < 10; ++u) {
                int e = ctf + u * 64;
                if (e < 625) {
                    int j2 = e / 25, c2 = e - j2 * 25;
                    unsigned h0 = pack_ex2_h2(A[u].x * L, B[u].x * L);
                    unsigned h1 = pack_ex2_h2(A[u].y * L, B[u].y * L);
                    *(uint2*)&Pf[1][j2 * 64 + 2 * c2] = make_uint2(h0, h1);
                }
            }
        }
        if (2 < nvF) {
            #pragma unroll
            for (int u = 0; u < 10; ++u) {
                int e = ctf + u * 64;
                if (e < 625) {
                    int j2 = e / 25, c2 = e - j2 * 25;
                    const float2* s = (const float2*)(base + (size_t)2 * KK + (2 * j2) * KDIM) + c2;
                    A[u] = __ldg(s); B[u] = __ldg(s + 25);
                }
            }
        }
        if (tid == 128) {
            gold = __ldg(base + __ldg(tgp + 0));
            gpend = (1 < nvF) ? __ldg(base + (size_t)1 * KK + __ldg(tgp + 1)) : 0.f;
        }
    } else {                          // bwd conv
        if (1 < nvB) {
            #pragma unroll
            for (int u = 0; u < 20; ++u) {
                int e = ctb + u * 64;
                if (e < 1250) {
                    int rr = e / 25, k2 = e - rr * 25;
                    Pb[1][rr * PBS + k2] = pack_ex2_h2(C[u].x * L, C[u].y * L);
                }
            }
        }
        if (2 < nvB) {
            #pragma unroll
            for (int u = 0; u < 20; ++u) {
                int e = ctb + u * 64;
                if (e < 1250) {
                    int rr = e / 25, k2 = e - rr * 25;
                    C[u] = __ldg((const float2*)(base + (size_t)(len - 2) * KK + rr * KDIM) + k2);
                }
            }
        }
        if (tid == 192) {
            gold = 0.f;
            gpend = (1 < nvB) ? __ldg(base + (size_t)(len - 1) * KK + __ldg(tgp + len - 1)) : 0.f;
        }
    }

    // ================= main phases =================
    for (int v = 1; v < nvB; ++v) {
        __syncthreads();              // P[v&1], w[v&1], r0s certified

        if (wid < 2) {                // fwd GEMV
            if (v < nvF) {
                const unsigned* pcol = Pf[v & 1] + cc;
                const unsigned* wp = (const unsigned*)wf[v & 1];
                __half2 a0 = __float2half2_rn(0.f), a1 = a0, a2 = a0, a3 = a0;
                #pragma unroll
                for (int j2 = 0; j2 < 25; ++j2) {
                    __half2 P2 = u2h(pcol[j2 * 64]);
                    __half2 W2 = u2h(wp[j2]);
                    if      ((j2 & 3) == 0) a0 = __hfma2(P2, W2, a0);
                    else if ((j2 & 3) == 1) a1 = __hfma2(P2, W2, a1);
                    else if ((j2 & 3) == 2) a2 = __hfma2(P2, W2, a2);
                    else                    a3 = __hfma2(P2, W2, a3);
                }
                float2 s0 = __half22float2(__hadd2(a0, a1));
                float2 s1 = __half22float2(__hadd2(a2, a3));
                float tot = (s0.x + s1.x) + (s0.y + s1.y);
                r = lg2f(fmaxf(tot, 1e-35f));
                shift += dcur;
                float dn = r0s[0][(v - 1) & 1] + SLACK;
                wf[(v + 1) & 1][c] = __float2half_rn(ex2f(fminf(r - dn, 4.0f)));
                dcur = dn;
                if (tid == 0) r0s[0][v & 1] = r;
            }
        } else if (wid < 4) {         // bwd GEMV (always active: v < nvB)
            const unsigned* prow = Pb[v & 1] + cc * PBS;
            const unsigned* wp = (const unsigned*)wb[v & 1];
            __half2 a0 = __float2half2_rn(0.f), a1 = a0, a2 = a0, a3 = a0;
            #pragma unroll
            for (int k2 = 0; k2 < 25; ++k2) {
                __half2 P2 = u2h(prow[k2]);
                __half2 W2 = u2h(wp[k2]);
                if      ((k2 & 3) == 0) a0 = __hfma2(P2, W2, a0);
                else if ((k2 & 3) == 1) a1 = __hfma2(P2, W2, a1);
                else if ((k2 & 3) == 2) a2 = __hfma2(P2, W2, a2);
                else                    a3 = __hfma2(P2, W2, a3);
            }
            float2 s0 = __half22float2(__hadd2(a0, a1));
            float2 s1 = __half22float2(__hadd2(a2, a3));
            float tot = (s0.x + s1.x) + (s0.y + s1.y);
            r = lg2f(fmaxf(tot, 1e-35f));
            shift += dcur;
            float dn = r0s[1][(v - 1) & 1] + SLACK;
            wb[(v + 1) & 1][c] = __float2half_rn(ex2f(fminf(r - dn, 4.0f)));
            dcur = dn;
            if (tid == 64) r0s[1][v & 1] = r;
        } else if (wid < 6) {         // fwd converter
            if (v + 1 < nvF) {        // staged regs hold tile v+1
                #pragma unroll
                for (int u = 0; u < 10; ++u) {
                    int e = ctf + u * 64;
                    if (e < 625) {
                        int j2 = e / 25, c2 = e - j2 * 25;
                        unsigned h0 = pack_ex2_h2(A[u].x * L, B[u].x * L);
                        unsigned h1 = pack_ex2_h2(A[u].y * L, B[u].y * L);
                        *(uint2*)&Pf[(v + 1) & 1][j2 * 64 + 2 * c2] = make_uint2(h0, h1);
                    }
                }
            }
            if (tid == 128) {
                gold += gpend;
                gpend = (v + 1 < nvF)
                    ? __ldg(base + (size_t)(v + 1) * KK + __ldg(tgp + v + 1)) : 0.f;
            }
            if (v + 3 < nvF) { const char* p = (const char*)(base + (size_t)(v + 3) * KK);
                               pfL2(p + ctf * 128); if (ctf < 15) pfL2(p + (ctf + 64) * 128); }
            if (v + 2 < nvF) {
                #pragma unroll
                for (int u = 0; u < 10; ++u) {
                    int e = ctf + u * 64;
                    if (e < 625) {
                        int j2 = e / 25, c2 = e - j2 * 25;
                        const float2* s = (const float2*)(base + (size_t)(v + 2) * KK + (2 * j2) * KDIM) + c2;
                        A[u] = __ldg(s); B[u] = __ldg(s + 25);
                    }
                }
            }
        } else {                      // bwd converter
            if (v + 1 < nvB) {
                #pragma unroll
                for (int u = 0; u < 20; ++u) {
                    int e = ctb + u * 64;
                    if (e < 1250) {
                        int rr = e / 25, k2 = e - rr * 25;
                        Pb[(v + 1) & 1][rr * PBS + k2] = pack_ex2_h2(C[u].x * L, C[u].y * L);
                    }
                }
            }
            if (tid == 192) {
                gold += gpend;
                gpend = (v + 1 < nvB)
                    ? __ldg(base + (size_t)(len - v - 1) * KK + __ldg(tgp + len - v - 1)) : 0.f;
            }
            if (v + 3 < nvB) { const char* p = (const char*)(base + (size_t)(len - v - 3) * KK);
                               pfL2(p + ctb * 128); if (ctb < 15) pfL2(p + (ctb + 64) * 128); }
            if (v + 2 < nvB) {
                #pragma unroll
                for (int u = 0; u < 20; ++u) {
                    int e = ctb + u * 64;
                    if (e < 1250) {
                        int rr = e / 25, k2 = e - rr * 25;
                        C[u] = __ldg((const float2*)(base + (size_t)(len - v - 2) * KK + rr * KDIM) + k2);
                    }
                }
            }
        }
    }

    // ================= combine =================
    if (wid < 4) {
        int dir = wid >> 1;
        avecs[dir][c] = (c < KDIM) ? (r + shift) : -1e30f;
    }
    if (tid == 128) goldS[0] = gold;
    if (tid == 192) goldS[1] = gold;
    __syncthreads();

    if (tid < 32) {
        int j2 = tid + 32;
        float x1 = avecs[0][tid] + avecs[1][tid];
        float x2 = (j2 < KDIM) ? (avecs[0][j2] + avecs[1][j2]) : -1e30f;
        float mx = fmaxf(x1, x2);
        #pragma unroll
        for (int o = 16; o > 0; o >>= 1)
            mx = fmaxf(mx, __shfl_xor_sync(0xFFFFFFFFu, mx, o));
        float s = ex2f(x1 - mx) + ex2f(x2 - mx);
        #pragma unroll
        for (int o = 16; o > 0; o >>= 1)
            s += __shfl_xor_sync(0xFFFFFFFFu, s, o);
        if (tid == 0) {
            g_apart[b] = (mx + lg2f(s)) * 0.6931471805599453f;
            g_gpart[b] = goldS[0] + goldS[1];
        }
    }
    __syncthreads();
    if (tid == 0) {
        __threadfence();
        int old = atomicAdd(&g_count, 1);
        sFin = (old == BB - 1) ? 1 : 0;
    }
    __syncthreads();

    if (sFin) {                       // last CTA: deterministic final reduce
        __threadfence();
        float a = 0.f, gd = 0.f;
        if (tid < BB) { a = g_apart[tid]; gd = g_gpart[tid]; }
        #pragma unroll
        for (int o = 16; o > 0; o >>= 1) {
            a  += __shfl_down_sync(0xFFFFFFFFu, a, o);
            gd += __shfl_down_sync(0xFFFFFFFFu, gd, o);
        }
        if (lane == 0) { sa[wid] = a; sg[wid] = gd; }
        __syncthreads();
        if (tid == 0) {
            float A2 = sa[0] + sa[1] + sa[2] + sa[3];
            float G2 = sg[0] + sg[1] + sg[2] + sg[3];
            out[0] = (A2 - G2) / (float)BB;
            atomicExch(&g_count, 0);  // reset for next graph replay
        }
    }
}

extern "C" void kernel_launch(void* const* d_in, const int* in_sizes, int n_in,
                              void* d_out, int out_size) {
    const float* scores  = (const float*)d_in[0];
    const int*   targets = (const int*)d_in[1];
    const int*   lengths = (const int*)d_in[2];
    // d_in[3] = tmap_correct (unused scalar)
    viterbi_gemv_kernel<<<BB, NTH>>>(scores, targets, lengths, (float*)d_out);
}